// round 16
// baseline (speedup 1.0000x reference)
#include <cuda_runtime.h>
#include <cstddef>

// 7x7 VALID conv, 4096x4096 fp32 -> 4090x4090 fp32, + bias.
// R16 = R15 (3 rows x 8 cols/thread, imm-offset LDG, P/Q weight-pair FFMA2 in
// __constant__, no smem/barriers) + shuffle halo (R14) + 1-row software
// prefetch so SHFL operands are a full iteration old (latency hidden by the
// previous row's FMA block).
// Block 16x8 = 128 thr; tile 128(w) x 24(h).

#define IN_W 4096
#define IN_H 4096
#define OUT_W 4090
#define OUT_H 4090

#define TILE_W 128
#define TILE_H 24

typedef unsigned long long u64;

__constant__ u64 c_wp[60];   // [kr*8+0..3]=P, [kr*8+4..7]=Q, [56]=(bias,bias)
__device__ u64 g_pack[60];

__device__ __forceinline__ u64 pk(float a, float b) {
    u64 r;
    asm("mov.b64 %0, {%1, %2};" : "=l"(r) : "f"(a), "f"(b));
    return r;
}
__device__ __forceinline__ void upk(u64 v, float &a, float &b) {
    asm("mov.b64 {%0, %1}, %2;" : "=f"(a), "=f"(b) : "l"(v));
}
__device__ __forceinline__ void fma2(u64 &d, u64 a, u64 b) {
    asm("fma.rn.f32x2 %0, %1, %2, %3;" : "=l"(d) : "l"(a), "l"(b), "l"(d));
}
__device__ __forceinline__ u64 shfld1(u64 v) {
    return __shfl_down_sync(0xffffffffu, v, 1, 16);
}

__global__ void prep_kernel(const float* __restrict__ w,
                            const float* __restrict__ bias)
{
    const int t = threadIdx.x;
    if (t < 7) {
        const float* wr = w + t * 7;
        float w0 = wr[0], w1 = wr[1], w2 = wr[2], w3 = wr[3],
              w4 = wr[4], w5 = wr[5], w6 = wr[6];
        g_pack[t * 8 + 0] = pk(w0, w1);
        g_pack[t * 8 + 1] = pk(w2, w3);
        g_pack[t * 8 + 2] = pk(w4, w5);
        g_pack[t * 8 + 3] = pk(w6, 0.f);
        g_pack[t * 8 + 4] = pk(0.f, w0);
        g_pack[t * 8 + 5] = pk(w1, w2);
        g_pack[t * 8 + 6] = pk(w3, w4);
        g_pack[t * 8 + 7] = pk(w5, w6);
    } else if (t == 7) {
        float b = bias[0];
        g_pack[56] = pk(b, b);
    } else if (t < 11) {
        g_pack[t + 50] = 0ull;   // pad 57..59
    }
}

__global__ __launch_bounds__(128)
void conv7x7_kernel(const float* __restrict__ x,
                    float* __restrict__ out)
{
    const int tx = threadIdx.x;     // 0..15
    const int ty = threadIdx.y;     // 0..7

    const int bx = blockIdx.x * TILE_W;
    const int by = blockIdx.y * TILE_H;

    const int gx = bx + tx * 8;     // input col base for this thread
    const int ry = by + ty * 3;     // first output row

    const bool is_edge = (tx == 15);           // halo self-load lane
    const bool c2ok = (gx + 12 <= IN_W);
    const bool c3ok = (gx + 14 <= IN_W);

    u64 acc[3][8];
    #pragma unroll
    for (int a = 0; a < 3; a++)
        #pragma unroll
        for (int j = 0; j < 8; j++) acc[a][j] = 0ull;

    const bool rows_fast = (ry + 8 <= IN_H - 1);
    const char* bp8 = reinterpret_cast<const char*>(x + (size_t)ry * IN_W + gx);

    // Row pointer helper (slow path only on the final row band)
    auto row_ptr = [&](int r) -> const char* {
        if (rows_fast) return bp8 + r * (IN_W * 4);
        int gy = ry + r; if (gy > IN_H - 1) gy = IN_H - 1;
        return reinterpret_cast<const char*>(x + (size_t)gy * IN_W + gx);
    };

    // Load own 32B + edge halo for a row
    u64 C[4];           // current row own pairs E0..E3
    u64 CH4, CH5, CH6;  // current row edge-lane halo
    u64 N[4];           // next row own pairs
    u64 NH4, NH5, NH6;  // next row edge halo

    {
        const char* rp = row_ptr(0);
        ulonglong2 q0 = *reinterpret_cast<const ulonglong2*>(rp);
        ulonglong2 q1 = *reinterpret_cast<const ulonglong2*>(rp + 16);
        C[0] = q0.x; C[1] = q0.y; C[2] = q1.x; C[3] = q1.y;
        CH4 = CH5 = CH6 = 0ull;
        if (is_edge) {
            if (c2ok) {
                ulonglong2 q2 = *reinterpret_cast<const ulonglong2*>(rp + 32);
                CH4 = q2.x; CH5 = q2.y;
            }
            if (c3ok) CH6 = *reinterpret_cast<const u64*>(rp + 48);
        }
    }

    #pragma unroll
    for (int r = 0; r < 9; r++) {
        // ---- Prefetch row r+1 (overlaps with this row's shuffles + FMAs) ----
        if (r < 8) {
            const char* rp = row_ptr(r + 1);
            ulonglong2 q0 = *reinterpret_cast<const ulonglong2*>(rp);
            ulonglong2 q1 = *reinterpret_cast<const ulonglong2*>(rp + 16);
            N[0] = q0.x; N[1] = q0.y; N[2] = q1.x; N[3] = q1.y;
            NH4 = NH5 = NH6 = 0ull;
            if (is_edge) {
                if (c2ok) {
                    ulonglong2 q2 = *reinterpret_cast<const ulonglong2*>(rp + 32);
                    NH4 = q2.x; NH5 = q2.y;
                }
                if (c3ok) NH6 = *reinterpret_cast<const u64*>(rp + 48);
            }
        }

        // ---- Halo for row r via shuffle (C regs are a full iteration old) ----
        u64 E[7];
        E[0] = C[0]; E[1] = C[1]; E[2] = C[2]; E[3] = C[3];
        E[4] = shfld1(C[0]);
        E[5] = shfld1(C[1]);
        E[6] = shfld1(C[2]);
        if (is_edge) { E[4] = CH4; E[5] = CH5; E[6] = CH6; }

        // ---- FMA block for row r ----
        #pragma unroll
        for (int ar = 0; ar < 3; ar++) {
            const int kr = r - ar;
            if (kr >= 0 && kr <= 6) {
                #pragma unroll
                for (int t = 0; t < 4; t++) {
                    const u64 Pt = c_wp[kr * 8 + t];
                    const u64 Qt = c_wp[kr * 8 + 4 + t];
                    #pragma unroll
                    for (int v = 0; v < 4; v++) {
                        fma2(acc[ar][2 * v],     E[v + t], Pt);
                        fma2(acc[ar][2 * v + 1], E[v + t], Qt);
                    }
                }
            }
        }

        // ---- Rotate pipeline ----
        if (r < 8) {
            C[0] = N[0]; C[1] = N[1]; C[2] = N[2]; C[3] = N[3];
            CH4 = NH4; CH5 = NH5; CH6 = NH6;
        }
    }

    // ---- Epilogue: out[j] = acc.lo + acc.hi + bias; float2 stores ----
    float bv, bdummy;
    upk(c_wp[56], bv, bdummy);
    #pragma unroll
    for (int ar = 0; ar < 3; ar++) {
        const int oy = ry + ar;
        if (oy < OUT_H) {
            float* orow = out + (size_t)oy * OUT_W;
            #pragma unroll
            for (int v = 0; v < 4; v++) {
                const int ox = gx + 2 * v;
                if (ox < OUT_W) {
                    float l0, h0, l1, h1;
                    upk(acc[ar][2 * v],     l0, h0);
                    upk(acc[ar][2 * v + 1], l1, h1);
                    float2 o;
                    o.x = l0 + h0 + bv;
                    o.y = l1 + h1 + bv;
                    *reinterpret_cast<float2*>(orow + ox) = o;
                }
            }
        }
    }
}

extern "C" void kernel_launch(void* const* d_in, const int* in_sizes, int n_in,
                              void* d_out, int out_size)
{
    const float* x    = (const float*)d_in[0];
    const float* w    = (const float*)d_in[1];
    const float* bias = (const float*)d_in[2];
    float* out = (float*)d_out;

    prep_kernel<<<1, 32>>>(w, bias);

    void* dst = nullptr;
    void* src = nullptr;
    cudaGetSymbolAddress(&dst, c_wp);
    cudaGetSymbolAddress(&src, g_pack);
    cudaMemcpyAsync(dst, src, 60 * sizeof(u64), cudaMemcpyDeviceToDevice);

    dim3 block(16, 8);
    dim3 grid((OUT_W + TILE_W - 1) / TILE_W,   // 32
              (OUT_H + TILE_H - 1) / TILE_H);  // 171
    conv7x7_kernel<<<grid, block>>>(x, out);
}